// round 10
// baseline (speedup 1.0000x reference)
#include <cuda_runtime.h>
#include <cuda_bf16.h>
#include <cstdint>

#define HDIM 2048
#define HH (HDIM*HDIM)
#define NBINS 256
#define ITEMS 8

// ---------------- device scratch (no allocations allowed) ----------------
__device__ unsigned int  g_pack_src[HH];       // 16MB: {b0,b1,b2,flag,cover} per pixel (ref/msrc)
__device__ unsigned int  g_pack_tar[HH];       // 16MB: {b0,b1,b2,flag} per pixel (tgt/mtar)
__device__ int           g_hist[6 * NBINS];    // [0..2]=dst(ref img), [3..5]=ref(target img)
__device__ float         g_tablef[3 * NBINS];
__device__ double        g_acc;

__device__ __forceinline__ int binof(float x) {
    float v = fmaf(x, 0.5f, 0.5f) * 255.0f;
    return min(max((int)floorf(v), 0), NBINS - 1);
}

// ---------------- kernel 1: pack pixels + zero scratch (streaming loads) ----------------
__global__ void __launch_bounds__(256) k_pack(
    const float* __restrict__ ref,   // (3,H,H)
    const float* __restrict__ tgt,   // (3,H,H)
    const float* __restrict__ msrc,  // (H,H)
    const float* __restrict__ mtar)  // (H,H)
{
    int t = blockIdx.x * blockDim.x + threadIdx.x;   // 0..HH/4-1
    if (t < HH / 4) {
        float4 m  = __ldcs((const float4*)msrc + t);
        float4 r0 = __ldcs((const float4*)(ref + 0 * HH) + t);
        float4 r1 = __ldcs((const float4*)(ref + 1 * HH) + t);
        float4 r2 = __ldcs((const float4*)(ref + 2 * HH) + t);
        float4 n  = __ldcs((const float4*)mtar + t);
        float4 t0 = __ldcs((const float4*)(tgt + 0 * HH) + t);
        float4 t1 = __ldcs((const float4*)(tgt + 1 * HH) + t);
        float4 t2 = __ldcs((const float4*)(tgt + 2 * HH) + t);

        float mv[4] = { m.x, m.y, m.z, m.w };
        float a0[4] = { r0.x, r0.y, r0.z, r0.w };
        float a1[4] = { r1.x, r1.y, r1.z, r1.w };
        float a2[4] = { r2.x, r2.y, r2.z, r2.w };
        float nv[4] = { n.x, n.y, n.z, n.w };
        float c0[4] = { t0.x, t0.y, t0.z, t0.w };
        float c1[4] = { t1.x, t1.y, t1.z, t1.w };
        float c2[4] = { t2.x, t2.y, t2.z, t2.w };

        uint4 ps, pt;
        unsigned int* psp = (unsigned int*)&ps;
        unsigned int* ptp = (unsigned int*)&pt;
        #pragma unroll
        for (int j = 0; j < 4; j++) {
            // cover bit (25) starts 0 every call -> graph-replay deterministic
            if (mv[j] != 0.0f) {
                psp[j] = (unsigned)binof(a0[j]) | ((unsigned)binof(a1[j]) << 8)
                       | ((unsigned)binof(a2[j]) << 16) | (1u << 24);
            } else psp[j] = 0u;
            if (nv[j] != 0.0f) {
                ptp[j] = (unsigned)binof(c0[j]) | ((unsigned)binof(c1[j]) << 8)
                       | ((unsigned)binof(c2[j]) << 16) | (1u << 24);
            } else ptp[j] = 0u;
        }
        ((uint4*)g_pack_src)[t] = ps;
        ((uint4*)g_pack_tar)[t] = pt;
    }
    if (blockIdx.x == 0) {
        for (int i = threadIdx.x; i < 6 * NBINS; i += blockDim.x) g_hist[i] = 0;
        if (threadIdx.x == 0) g_acc = 0.0;
    }
}

// ---------------- kernel 2: gather histograms + coverage bit (4 replicas) ----------------
__global__ void __launch_bounds__(256) k_hist(
    const int* __restrict__ i0, const int* __restrict__ i1,
    const int* __restrict__ i2, const int* __restrict__ i3,
    int n)
{
    // 4 replicas selected by warp&3 (reduces cross-warp conflict replays)
    __shared__ int sh[4][6 * NBINS];
    for (int t = threadIdx.x; t < 6 * NBINS; t += blockDim.x) {
        sh[0][t] = 0; sh[1][t] = 0; sh[2][t] = 0; sh[3][t] = 0;
    }
    __syncthreads();

    const int tot  = gridDim.x * blockDim.x;
    const int tid  = blockIdx.x * blockDim.x + threadIdx.x;
    const int lane = threadIdx.x & 31;
    int* hist = sh[(threadIdx.x >> 5) & 3];
    int zcd = 0, zcr = 0;
    // channel rotation: lane l starts at channel l%3 -> decorrelates same-bin replays
    const int cr0 = lane % 3;
    const int cr1 = (cr0 + 1) % 3;
    const int cr2 = (cr0 + 2) % 3;

    // each thread handles ITEMS consecutive items -> int4 idx loads (LDG.128)
    for (int base = tid * ITEMS; base < n; base += tot * ITEMS) {
        int  pd[ITEMS], pr[ITEMS];
        bool va[ITEMS];
        unsigned int ps[ITEMS], pt[ITEMS];

        if (base + ITEMS <= n) {
            // fast path: vectorized 128-bit index loads (base is 8-aligned)
            int4 a0 = __ldg((const int4*)(i0 + base));
            int4 a1 = __ldg((const int4*)(i0 + base) + 1);
            int4 b0 = __ldg((const int4*)(i1 + base));
            int4 b1 = __ldg((const int4*)(i1 + base) + 1);
            int4 c0 = __ldg((const int4*)(i2 + base));
            int4 c1 = __ldg((const int4*)(i2 + base) + 1);
            int4 d0 = __ldg((const int4*)(i3 + base));
            int4 d1 = __ldg((const int4*)(i3 + base) + 1);
            int av[ITEMS] = { a0.x, a0.y, a0.z, a0.w, a1.x, a1.y, a1.z, a1.w };
            int bv[ITEMS] = { b0.x, b0.y, b0.z, b0.w, b1.x, b1.y, b1.z, b1.w };
            int cv[ITEMS] = { c0.x, c0.y, c0.z, c0.w, c1.x, c1.y, c1.z, c1.w };
            int dv[ITEMS] = { d0.x, d0.y, d0.z, d0.w, d1.x, d1.y, d1.z, d1.w };
            #pragma unroll
            for (int j = 0; j < ITEMS; j++) {
                va[j] = true;
                pd[j] = av[j] * HDIM + bv[j];
                pr[j] = cv[j] * HDIM + dv[j];
            }
        } else {
            #pragma unroll
            for (int j = 0; j < ITEMS; j++) {
                int idx = base + j;
                va[j] = (idx < n);
                int a = va[j] ? __ldg(i0 + idx) : 0;
                int b = va[j] ? __ldg(i1 + idx) : 0;
                int c = va[j] ? __ldg(i2 + idx) : 0;
                int d = va[j] ? __ldg(i3 + idx) : 0;
                pd[j] = a * HDIM + b;
                pr[j] = c * HDIM + d;
            }
        }

        #pragma unroll
        for (int j = 0; j < ITEMS; j++) {
            ps[j] = va[j] ? __ldg(g_pack_src + pd[j]) : 0u;
            pt[j] = va[j] ? __ldg(g_pack_tar + pr[j]) : 0u;
        }
        // coverage: set bit25 in the pack word; skip if observed already set
        // (safe: bit only transitions 0->1 within this launch)
        #pragma unroll
        for (int j = 0; j < ITEMS; j++)
            if (va[j] && !((ps[j] >> 25) & 1u)) atomicOr(&g_pack_src[pd[j]], 1u << 25);
        #pragma unroll
        for (int j = 0; j < ITEMS; j++) {
            if (!va[j]) continue;
            unsigned int w = ps[j];
            if ((w >> 24) & 1u) {
                atomicAdd(&hist[cr0 * NBINS + ((w >> (8 * cr0)) & 0xff)], 1);
                atomicAdd(&hist[cr1 * NBINS + ((w >> (8 * cr1)) & 0xff)], 1);
                atomicAdd(&hist[cr2 * NBINS + ((w >> (8 * cr2)) & 0xff)], 1);
            } else zcd++;
            unsigned int u = pt[j];
            if ((u >> 24) & 1u) {
                atomicAdd(&hist[(3 + cr0) * NBINS + ((u >> (8 * cr0)) & 0xff)], 1);
                atomicAdd(&hist[(3 + cr1) * NBINS + ((u >> (8 * cr1)) & 0xff)], 1);
                atomicAdd(&hist[(3 + cr2) * NBINS + ((u >> (8 * cr2)) & 0xff)], 1);
            } else zcr++;
        }
    }

    if (zcd) {
        atomicAdd(&hist[0 * NBINS], zcd);
        atomicAdd(&hist[1 * NBINS], zcd);
        atomicAdd(&hist[2 * NBINS], zcd);
    }
    if (zcr) {
        atomicAdd(&hist[3 * NBINS], zcr);
        atomicAdd(&hist[4 * NBINS], zcr);
        atomicAdd(&hist[5 * NBINS], zcr);
    }
    __syncthreads();
    for (int t = threadIdx.x; t < 6 * NBINS; t += blockDim.x) {
        int v = sh[0][t] + sh[1][t] + sh[2][t] + sh[3][t];
        if (v) atomicAdd(&g_hist[t], v);
    }
}

// ---------------- kernel 3: cdf + transfer table (parallel int scan) ----------------
__global__ void k_table() {
    __shared__ int sa[NBINS], sb[NBINS];      // scan buffers (dst side)
    __shared__ int ta[NBINS], tb[NBINS];      // scan buffers (ref side)
    __shared__ float cdf_d[NBINS], cdf_r[NBINS];
    int i = threadIdx.x;
    for (int c = 0; c < 3; c++) {
        sa[i] = g_hist[c * NBINS + i];
        ta[i] = g_hist[(3 + c) * NBINS + i];
        __syncthreads();
        // Hillis-Steele inclusive scan (int -> exact)
        int* src_s = sa; int* dst_s = sb;
        int* src_t = ta; int* dst_t = tb;
        #pragma unroll
        for (int off = 1; off < NBINS; off <<= 1) {
            int vs = src_s[i] + (i >= off ? src_s[i - off] : 0);
            int vt = src_t[i] + (i >= off ? src_t[i - off] : 0);
            dst_s[i] = vs; dst_t[i] = vt;
            __syncthreads();
            int* tmp = src_s; src_s = dst_s; dst_s = tmp;
            tmp = src_t; src_t = dst_t; dst_t = tmp;
        }
        float tot_s = (float)src_s[NBINS - 1];
        float tot_t = (float)src_t[NBINS - 1];
        cdf_d[i] = (float)src_s[i] / tot_s;
        cdf_r[i] = (float)src_t[i] / tot_t;
        __syncthreads();
        int res;
        if (i == 0)              res = 0;
        else if (i == NBINS - 1) res = NBINS - 1;
        else {
            res = i;  // default when not found
            float r = cdf_d[i];
            for (int j = 0; j < NBINS - 1; j++) {
                if (cdf_r[j] <= r && r <= cdf_r[j + 1]) { res = j + 1; break; }
            }
        }
        g_tablef[c * NBINS + i] = (float)res;
        __syncthreads();
    }
}

// ---------------- kernel 4: streaming L1-loss reduction (pack-word driven) ----------------
#define RITEMS 4
__global__ void __launch_bounds__(256) k_reduce(
    const float* __restrict__ inp,   // (3,H,H)
    const float* __restrict__ ref)   // (3,H,H)
{
    __shared__ float stab[3 * NBINS];
    for (int t = threadIdx.x; t < 3 * NBINS; t += blockDim.x) stab[t] = g_tablef[t];
    __syncthreads();

    float local = 0.0f;
    const int stride = gridDim.x * blockDim.x;
    const int tid = blockIdx.x * blockDim.x + threadIdx.x;

    #pragma unroll
    for (int it = 0; it < RITEMS; it++) {
        int p4 = tid + it * stride;
        if (p4 >= HH / 4) break;
        uint4 pw4 = ((const uint4*)g_pack_src)[p4];
        unsigned int pw[4] = { pw4.x, pw4.y, pw4.z, pw4.w };
        #pragma unroll
        for (int c = 0; c < 3; c++) {
            float4 a4 = __ldcs((const float4*)(inp + c * HH) + p4);
            float4 r4 = __ldcs((const float4*)(ref + c * HH) + p4);
            float av[4] = { a4.x, a4.y, a4.z, a4.w };
            float rv[4] = { r4.x, r4.y, r4.z, r4.w };
            #pragma unroll
            for (int t = 0; t < 4; t++) {
                unsigned int w = pw[t];
                float a = fmaf(av[t], 0.5f, 0.5f) * 255.0f;
                float r = fmaf(rv[t], 0.5f, 0.5f) * 255.0f;
                int b = (w >> (8 * c)) & 0xff;          // precomputed bin of r
                float mapped = stab[c * NBINS + b];
                bool cov = (w >> 25) & 1u;
                float mval = cov ? mapped : r;
                float term = fabsf(a - mval);
                local += ((w >> 24) & 1u) ? term : 0.0f;  // mask flag
            }
        }
    }

    double dl = (double)local;
    #pragma unroll
    for (int o = 16; o > 0; o >>= 1)
        dl += __shfl_down_sync(0xffffffffu, dl, o);
    __shared__ double wsum[8];
    if ((threadIdx.x & 31) == 0) wsum[threadIdx.x >> 5] = dl;
    __syncthreads();
    if (threadIdx.x < 8) {
        double v = wsum[threadIdx.x];
        #pragma unroll
        for (int o = 4; o > 0; o >>= 1)
            v += __shfl_down_sync(0xffu, v, o);
        if (threadIdx.x == 0) atomicAdd(&g_acc, v);
    }
}

// ---------------- kernel 5: finalize ----------------
__global__ void k_final(float* out) {
    out[0] = (float)(g_acc / (3.0 * (double)HH));
}

// ---------------- launcher ----------------
extern "C" void kernel_launch(void* const* d_in, const int* in_sizes, int n_in,
                              void* d_out, int out_size) {
    const float* input_data = (const float*)d_in[0];
    const float* target_data = (const float*)d_in[1];
    const float* mask_src = (const float*)d_in[2];
    const float* mask_tar = (const float*)d_in[3];
    const int* idx0 = (const int*)d_in[4];
    const int* idx1 = (const int*)d_in[5];
    const int* idx2 = (const int*)d_in[6];
    const int* idx3 = (const int*)d_in[7];
    const float* ref = (const float*)d_in[8];
    const int N = in_sizes[4];

    k_pack<<<4096, 256>>>(ref, target_data, mask_src, mask_tar);
    k_hist<<<1024, 256>>>(idx0, idx1, idx2, idx3, N);
    k_table<<<1, 256>>>();
    k_reduce<<<1024, 256>>>(input_data, ref);   // 1024*256*4 = HH/4 exactly
    k_final<<<1, 1>>>((float*)d_out);
}

// round 11
// speedup vs baseline: 1.0906x; 1.0906x over previous
#include <cuda_runtime.h>
#include <cuda_bf16.h>
#include <cstdint>

#define HDIM 2048
#define HH (HDIM*HDIM)
#define NBINS 256
#define ITEMS 8

// ---------------- device scratch (no allocations allowed) ----------------
__device__ unsigned int  g_pack_src[HH];       // 16MB: {b0,b1,b2,flag,cover} per pixel (ref/msrc)
__device__ unsigned int  g_pack_tar[HH];       // 16MB: {b0,b1,b2,flag} per pixel (tgt/mtar)
__device__ int           g_hist[6 * NBINS];    // [0..2]=dst(ref img), [3..5]=ref(target img)
__device__ float         g_tablef[3 * NBINS];
__device__ double        g_acc;
__device__ unsigned int  g_done_r;

__device__ __forceinline__ int binof(float x) {
    float v = fmaf(x, 0.5f, 0.5f) * 255.0f;
    return min(max((int)floorf(v), 0), NBINS - 1);
}

// ---------------- kernel 1: pack pixels + zero scratch (streaming loads) ----------------
__global__ void __launch_bounds__(256) k_pack(
    const float* __restrict__ ref,   // (3,H,H)
    const float* __restrict__ tgt,   // (3,H,H)
    const float* __restrict__ msrc,  // (H,H)
    const float* __restrict__ mtar)  // (H,H)
{
    int t = blockIdx.x * blockDim.x + threadIdx.x;   // 0..HH/4-1
    if (t < HH / 4) {
        float4 m  = __ldcs((const float4*)msrc + t);
        float4 r0 = __ldcs((const float4*)(ref + 0 * HH) + t);
        float4 r1 = __ldcs((const float4*)(ref + 1 * HH) + t);
        float4 r2 = __ldcs((const float4*)(ref + 2 * HH) + t);
        float4 n  = __ldcs((const float4*)mtar + t);
        float4 t0 = __ldcs((const float4*)(tgt + 0 * HH) + t);
        float4 t1 = __ldcs((const float4*)(tgt + 1 * HH) + t);
        float4 t2 = __ldcs((const float4*)(tgt + 2 * HH) + t);

        float mv[4] = { m.x, m.y, m.z, m.w };
        float a0[4] = { r0.x, r0.y, r0.z, r0.w };
        float a1[4] = { r1.x, r1.y, r1.z, r1.w };
        float a2[4] = { r2.x, r2.y, r2.z, r2.w };
        float nv[4] = { n.x, n.y, n.z, n.w };
        float c0[4] = { t0.x, t0.y, t0.z, t0.w };
        float c1[4] = { t1.x, t1.y, t1.z, t1.w };
        float c2[4] = { t2.x, t2.y, t2.z, t2.w };

        uint4 ps, pt;
        unsigned int* psp = (unsigned int*)&ps;
        unsigned int* ptp = (unsigned int*)&pt;
        #pragma unroll
        for (int j = 0; j < 4; j++) {
            // cover bit (25) starts 0 every call -> graph-replay deterministic
            if (mv[j] != 0.0f) {
                psp[j] = (unsigned)binof(a0[j]) | ((unsigned)binof(a1[j]) << 8)
                       | ((unsigned)binof(a2[j]) << 16) | (1u << 24);
            } else psp[j] = 0u;
            if (nv[j] != 0.0f) {
                ptp[j] = (unsigned)binof(c0[j]) | ((unsigned)binof(c1[j]) << 8)
                       | ((unsigned)binof(c2[j]) << 16) | (1u << 24);
            } else ptp[j] = 0u;
        }
        ((uint4*)g_pack_src)[t] = ps;
        ((uint4*)g_pack_tar)[t] = pt;
    }
    if (blockIdx.x == 0) {
        for (int i = threadIdx.x; i < 6 * NBINS; i += blockDim.x) g_hist[i] = 0;
        if (threadIdx.x == 0) { g_acc = 0.0; g_done_r = 0u; }
    }
}

// ---------------- kernel 2: gather histograms + coverage bit (4 replicas) ----------------
__global__ void __launch_bounds__(256) k_hist(
    const int* __restrict__ i0, const int* __restrict__ i1,
    const int* __restrict__ i2, const int* __restrict__ i3,
    int n)
{
    // 4 replicas selected by warp&3 (reduces cross-warp conflict replays)
    __shared__ int sh[4][6 * NBINS];
    for (int t = threadIdx.x; t < 6 * NBINS; t += blockDim.x) {
        sh[0][t] = 0; sh[1][t] = 0; sh[2][t] = 0; sh[3][t] = 0;
    }
    __syncthreads();

    const int tot  = gridDim.x * blockDim.x;
    const int tid  = blockIdx.x * blockDim.x + threadIdx.x;
    const int lane = threadIdx.x & 31;
    int* hist = sh[(threadIdx.x >> 5) & 3];
    int zcd = 0, zcr = 0;
    // channel rotation: lane l starts at channel l%3 -> decorrelates same-bin replays
    const int cr0 = lane % 3;
    const int cr1 = (cr0 + 1) % 3;
    const int cr2 = (cr0 + 2) % 3;

    for (int base = 0; base < n; base += tot * ITEMS) {
        int  pd[ITEMS], pr[ITEMS];
        bool va[ITEMS];
        unsigned int ps[ITEMS], pt[ITEMS];

        #pragma unroll
        for (int j = 0; j < ITEMS; j++) {
            int idx = base + j * tot + tid;
            va[j] = (idx < n);
            int a = va[j] ? __ldg(i0 + idx) : 0;
            int b = va[j] ? __ldg(i1 + idx) : 0;
            int c = va[j] ? __ldg(i2 + idx) : 0;
            int d = va[j] ? __ldg(i3 + idx) : 0;
            pd[j] = a * HDIM + b;
            pr[j] = c * HDIM + d;
        }
        #pragma unroll
        for (int j = 0; j < ITEMS; j++) {
            ps[j] = va[j] ? __ldg(g_pack_src + pd[j]) : 0u;
            pt[j] = va[j] ? __ldg(g_pack_tar + pr[j]) : 0u;
        }
        // coverage: set bit25 in the pack word; skip if observed already set
        // (safe: bit only transitions 0->1 within this launch)
        #pragma unroll
        for (int j = 0; j < ITEMS; j++)
            if (va[j] && !((ps[j] >> 25) & 1u)) atomicOr(&g_pack_src[pd[j]], 1u << 25);
        #pragma unroll
        for (int j = 0; j < ITEMS; j++) {
            if (!va[j]) continue;
            unsigned int w = ps[j];
            if ((w >> 24) & 1u) {
                atomicAdd(&hist[cr0 * NBINS + ((w >> (8 * cr0)) & 0xff)], 1);
                atomicAdd(&hist[cr1 * NBINS + ((w >> (8 * cr1)) & 0xff)], 1);
                atomicAdd(&hist[cr2 * NBINS + ((w >> (8 * cr2)) & 0xff)], 1);
            } else zcd++;
            unsigned int u = pt[j];
            if ((u >> 24) & 1u) {
                atomicAdd(&hist[(3 + cr0) * NBINS + ((u >> (8 * cr0)) & 0xff)], 1);
                atomicAdd(&hist[(3 + cr1) * NBINS + ((u >> (8 * cr1)) & 0xff)], 1);
                atomicAdd(&hist[(3 + cr2) * NBINS + ((u >> (8 * cr2)) & 0xff)], 1);
            } else zcr++;
        }
    }

    if (zcd) {
        atomicAdd(&hist[0 * NBINS], zcd);
        atomicAdd(&hist[1 * NBINS], zcd);
        atomicAdd(&hist[2 * NBINS], zcd);
    }
    if (zcr) {
        atomicAdd(&hist[3 * NBINS], zcr);
        atomicAdd(&hist[4 * NBINS], zcr);
        atomicAdd(&hist[5 * NBINS], zcr);
    }
    __syncthreads();
    for (int t = threadIdx.x; t < 6 * NBINS; t += blockDim.x) {
        int v = sh[0][t] + sh[1][t] + sh[2][t] + sh[3][t];
        if (v) atomicAdd(&g_hist[t], v);
    }
}

// ---------------- kernel 3: cdf + transfer table (parallel int scan) ----------------
__global__ void k_table() {
    __shared__ int sa[NBINS], sb[NBINS];      // scan buffers (dst side)
    __shared__ int ta[NBINS], tb[NBINS];      // scan buffers (ref side)
    __shared__ float cdf_d[NBINS], cdf_r[NBINS];
    int i = threadIdx.x;
    for (int c = 0; c < 3; c++) {
        sa[i] = g_hist[c * NBINS + i];
        ta[i] = g_hist[(3 + c) * NBINS + i];
        __syncthreads();
        // Hillis-Steele inclusive scan (int -> exact)
        int* src_s = sa; int* dst_s = sb;
        int* src_t = ta; int* dst_t = tb;
        #pragma unroll
        for (int off = 1; off < NBINS; off <<= 1) {
            int vs = src_s[i] + (i >= off ? src_s[i - off] : 0);
            int vt = src_t[i] + (i >= off ? src_t[i - off] : 0);
            dst_s[i] = vs; dst_t[i] = vt;
            __syncthreads();
            int* tmp = src_s; src_s = dst_s; dst_s = tmp;
            tmp = src_t; src_t = dst_t; dst_t = tmp;
        }
        float tot_s = (float)src_s[NBINS - 1];
        float tot_t = (float)src_t[NBINS - 1];
        cdf_d[i] = (float)src_s[i] / tot_s;
        cdf_r[i] = (float)src_t[i] / tot_t;
        __syncthreads();
        int res;
        if (i == 0)              res = 0;
        else if (i == NBINS - 1) res = NBINS - 1;
        else {
            res = i;  // default when not found
            float r = cdf_d[i];
            for (int j = 0; j < NBINS - 1; j++) {
                if (cdf_r[j] <= r && r <= cdf_r[j + 1]) { res = j + 1; break; }
            }
        }
        g_tablef[c * NBINS + i] = (float)res;
        __syncthreads();
    }
}

// ---------------- kernel 4: streaming L1-loss reduction + last-block finalize ----------------
#define RITEMS 4
__global__ void __launch_bounds__(256) k_reduce(
    const float* __restrict__ inp,   // (3,H,H)
    const float* __restrict__ ref,   // (3,H,H)
    float* __restrict__ out)
{
    __shared__ float stab[3 * NBINS];
    for (int t = threadIdx.x; t < 3 * NBINS; t += blockDim.x) stab[t] = g_tablef[t];
    __syncthreads();

    float local = 0.0f;
    const int stride = gridDim.x * blockDim.x;
    const int tid = blockIdx.x * blockDim.x + threadIdx.x;

    #pragma unroll
    for (int it = 0; it < RITEMS; it++) {
        int p4 = tid + it * stride;
        if (p4 >= HH / 4) break;
        uint4 pw4 = ((const uint4*)g_pack_src)[p4];
        unsigned int pw[4] = { pw4.x, pw4.y, pw4.z, pw4.w };
        #pragma unroll
        for (int c = 0; c < 3; c++) {
            float4 a4 = __ldcs((const float4*)(inp + c * HH) + p4);
            float4 r4 = __ldcs((const float4*)(ref + c * HH) + p4);
            float av[4] = { a4.x, a4.y, a4.z, a4.w };
            float rv[4] = { r4.x, r4.y, r4.z, r4.w };
            #pragma unroll
            for (int t = 0; t < 4; t++) {
                unsigned int w = pw[t];
                float a = fmaf(av[t], 0.5f, 0.5f) * 255.0f;
                float r = fmaf(rv[t], 0.5f, 0.5f) * 255.0f;
                int b = (w >> (8 * c)) & 0xff;          // precomputed bin of r
                float mapped = stab[c * NBINS + b];
                bool cov = (w >> 25) & 1u;
                float mval = cov ? mapped : r;
                float term = fabsf(a - mval);
                local += ((w >> 24) & 1u) ? term : 0.0f;  // mask flag
            }
        }
    }

    double dl = (double)local;
    #pragma unroll
    for (int o = 16; o > 0; o >>= 1)
        dl += __shfl_down_sync(0xffffffffu, dl, o);
    __shared__ double wsum[8];
    if ((threadIdx.x & 31) == 0) wsum[threadIdx.x >> 5] = dl;
    __syncthreads();
    if (threadIdx.x < 8) {
        double v = wsum[threadIdx.x];
        #pragma unroll
        for (int o = 4; o > 0; o >>= 1)
            v += __shfl_down_sync(0xffu, v, o);
        if (threadIdx.x == 0) atomicAdd(&g_acc, v);
    }

    // ---- last-block finalize (1-thread epilogue) ----
    if (threadIdx.x == 0) {
        __threadfence();
        if (atomicAdd(&g_done_r, 1u) == gridDim.x - 1) {
            double total = atomicAdd(&g_acc, 0.0);   // coherent read after fence
            out[0] = (float)(total / (3.0 * (double)HH));
        }
    }
}

// ---------------- launcher ----------------
extern "C" void kernel_launch(void* const* d_in, const int* in_sizes, int n_in,
                              void* d_out, int out_size) {
    const float* input_data = (const float*)d_in[0];
    const float* target_data = (const float*)d_in[1];
    const float* mask_src = (const float*)d_in[2];
    const float* mask_tar = (const float*)d_in[3];
    const int* idx0 = (const int*)d_in[4];
    const int* idx1 = (const int*)d_in[5];
    const int* idx2 = (const int*)d_in[6];
    const int* idx3 = (const int*)d_in[7];
    const float* ref = (const float*)d_in[8];
    const int N = in_sizes[4];

    k_pack<<<4096, 256>>>(ref, target_data, mask_src, mask_tar);
    k_hist<<<1024, 256>>>(idx0, idx1, idx2, idx3, N);
    k_table<<<1, 256>>>();
    k_reduce<<<1024, 256>>>(input_data, ref, (float*)d_out);   // 1024*256*4 = HH/4 exactly
}